// round 4
// baseline (speedup 1.0000x reference)
#include <cuda_runtime.h>
#include <math.h>
#include <complex>

// ---------------- problem constants ----------------
#define TT    16384          // time steps (output rows)
#define BB    512            // batch columns
#define TPAD  16388          // TT + K - 1 (K = 5)
#define LBLK  256            // IIR parallel block length
#define NBLK  64             // number of IIR blocks (16379 steps -> 64 blocks)
#define NU    63             // number of block transitions (u_k for k = 0..62)

// ---------------- device scratch (static, allocation-free) ----------------
__device__ float  g_sd[TPAD];          // noise std-dev per padded time step
__device__ float  g_s[TT * BB];        // FIR output s[t][b]
__device__ float  g_u[4 * NU * BB];    // block-transition input vectors
__device__ float4 g_states[NBLK * BB]; // IIR state at each block start

struct GP  { float g[LBLK]; };   // impulse response of 1/A (truncated)
struct ALP { float al[16]; };    // A^LBLK  (row-major 4x4)

// ---------------- kernel 1: noise std-dev per time step ----------------
// sd[t] = sqrt(C1*(mean_b xp[b,t]) + ADD), xp row t maps to signal row t-4 (zero for t<4)
__global__ __launch_bounds__(128) void k_sd(const float* __restrict__ sig,
                                            float c1, float addc) {
    int t = blockIdx.x;
    float sum = 0.f;
    if (t >= 4) {
        const float4* row = (const float4*)(sig + (size_t)(t - 4) * BB);
        float4 v = row[threadIdx.x];
        sum = (v.x + v.y) + (v.z + v.w);
    }
    #pragma unroll
    for (int o = 16; o; o >>= 1) sum += __shfl_down_sync(0xffffffffu, sum, o);
    __shared__ float red[4];
    if ((threadIdx.x & 31) == 0) red[threadIdx.x >> 5] = sum;
    __syncthreads();
    if (threadIdx.x == 0) {
        float tot = (red[0] + red[1]) + (red[2] + red[3]);
        g_sd[t] = sqrtf(fmaf(c1, tot * (1.f / 512.f), addc));
    }
}

// ---------------- kernel 2: xn + 5-tap FIR -> s[t][b]  (also out rows 0..4) ----------------
// s[t,b] = sum_k bk * ( sd[t+k]*noise[b][t+k] + signal[t+k-4][b] )
__global__ __launch_bounds__(256) void k_fir(const float* __restrict__ sig,
                                             const float* __restrict__ noise,
                                             float* __restrict__ out,
                                             float b0, float b1, float b2, float b3, float b4) {
    __shared__ float nz[32][69];   // [col][j], stride 69 -> conflict-free transpose reads
    __shared__ float sg[68][33];   // [j][col]
    __shared__ float sds[68];
    int tx = threadIdx.x, ty = threadIdx.y;
    int col0 = blockIdx.x * 32;
    int t0   = blockIdx.y * 64;

    // noise tile: rows = columns of the problem, coalesced along t
    #pragma unroll
    for (int i = 0; i < 4; i++) {
        int c = ty * 4 + i;
        const float* nrow = noise + (size_t)(col0 + c) * TPAD + t0;
        for (int j = tx; j < 68; j += 32) nz[c][j] = nrow[j];
    }
    // signal tile: coalesced along b
    for (int r = ty; r < 68; r += 8) {
        int trow = t0 - 4 + r;
        sg[r][tx] = (trow >= 0) ? sig[(size_t)trow * BB + col0 + tx] : 0.f;
    }
    int tid = ty * 32 + tx;
    if (tid < 68) sds[tid] = g_sd[t0 + tid];
    __syncthreads();

    #pragma unroll
    for (int i = 0; i < 8; i++) {
        int tt = ty + 8 * i;                       // local t 0..63
        float x0 = fmaf(sds[tt + 0], nz[tx][tt + 0], sg[tt + 0][tx]);
        float x1 = fmaf(sds[tt + 1], nz[tx][tt + 1], sg[tt + 1][tx]);
        float x2 = fmaf(sds[tt + 2], nz[tx][tt + 2], sg[tt + 2][tx]);
        float x3 = fmaf(sds[tt + 3], nz[tx][tt + 3], sg[tt + 3][tx]);
        float x4 = fmaf(sds[tt + 4], nz[tx][tt + 4], sg[tt + 4][tx]);
        float acc = b0 * x0;
        acc = fmaf(b1, x1, acc);
        acc = fmaf(b2, x2, acc);
        acc = fmaf(b3, x3, acc);
        acc = fmaf(b4, x4, acc);
        int t = t0 + tt;
        g_s[(size_t)t * BB + col0 + tx] = acc;
        if (t < 5) out[(size_t)t * BB + col0 + tx] = acc;   // out rows 0..4 = s rows 0..4
    }
}

// ---------------- pass A: per-(col, block) FIRs with g (block input vectors u_k) ----------------
// u_k[c] = sum_{i=0}^{LBLK-1-c} g_i * s[e - c - i],  e = 4 + LBLK*(k+1)
__global__ __launch_bounds__(128) void k_ua(GP P) {
    __shared__ float gs[LBLK];
    int tx = threadIdx.x, ty = threadIdx.y;
    int tid = ty * 32 + tx;
    for (int i = tid; i < LBLK; i += 128) gs[i] = P.g[i];
    __syncthreads();

    int k = blockIdx.y * 4 + ty;
    if (k >= NU) return;
    int col = blockIdx.x * 32 + tx;
    const float* sp = g_s + col;
    int e = 4 + LBLK * (k + 1);

    float u0, u1, u2, u3 = 0.f;
    float sv;
    sv = sp[(size_t)e * BB];
    u0 = gs[0] * sv;
    sv = sp[(size_t)(e - 1) * BB];
    u0 = fmaf(gs[1], sv, u0); u1 = gs[0] * sv;
    sv = sp[(size_t)(e - 2) * BB];
    u0 = fmaf(gs[2], sv, u0); u1 = fmaf(gs[1], sv, u1); u2 = gs[0] * sv;
    #pragma unroll 4
    for (int j = 3; j < LBLK; j++) {
        float s2 = sp[(size_t)(e - j) * BB];
        u0 = fmaf(gs[j],     s2, u0);
        u1 = fmaf(gs[j - 1], s2, u1);
        u2 = fmaf(gs[j - 2], s2, u2);
        u3 = fmaf(gs[j - 3], s2, u3);
    }
    g_u[0 * (NU * BB) + k * BB + col] = u0;
    g_u[1 * (NU * BB) + k * BB + col] = u1;
    g_u[2 * (NU * BB) + k * BB + col] = u2;
    g_u[3 * (NU * BB) + k * BB + col] = u3;
}

// ---------------- pass B: boundary-state chain (63 tiny 4x4 matvecs per column) ----------------
__global__ __launch_bounds__(128) void k_chain(ALP P) {
    int col = blockIdx.x * blockDim.x + threadIdx.x;
    if (col >= BB) return;
    // v_4 = [y4,y3,y2,y1] = [s4,s3,s2,s1]
    float v0 = g_s[4 * BB + col];
    float v1 = g_s[3 * BB + col];
    float v2 = g_s[2 * BB + col];
    float v3 = g_s[1 * BB + col];
    g_states[col] = make_float4(v0, v1, v2, v3);
    const float* al = P.al;
    for (int k = 0; k < NU; k++) {
        float w0 = g_u[0 * (NU * BB) + k * BB + col];
        w0 = fmaf(al[0],  v0, w0); w0 = fmaf(al[1],  v1, w0);
        w0 = fmaf(al[2],  v2, w0); w0 = fmaf(al[3],  v3, w0);
        float w1 = g_u[1 * (NU * BB) + k * BB + col];
        w1 = fmaf(al[4],  v0, w1); w1 = fmaf(al[5],  v1, w1);
        w1 = fmaf(al[6],  v2, w1); w1 = fmaf(al[7],  v3, w1);
        float w2 = g_u[2 * (NU * BB) + k * BB + col];
        w2 = fmaf(al[8],  v0, w2); w2 = fmaf(al[9],  v1, w2);
        w2 = fmaf(al[10], v2, w2); w2 = fmaf(al[11], v3, w2);
        float w3 = g_u[3 * (NU * BB) + k * BB + col];
        w3 = fmaf(al[12], v0, w3); w3 = fmaf(al[13], v1, w3);
        w3 = fmaf(al[14], v2, w3); w3 = fmaf(al[15], v3, w3);
        g_states[(k + 1) * BB + col] = make_float4(w0, w1, w2, w3);
        v0 = w0; v1 = w1; v2 = w2; v3 = w3;
    }
}

// ---------------- pass C: within-block IIR, 32768 independent threads ----------------
__global__ __launch_bounds__(256) void k_iir(float* __restrict__ out,
                                             float na1, float na2, float na3, float na4) {
    int tx = threadIdx.x, ty = threadIdx.y;
    int col = blockIdx.x * 32 + tx;
    int k   = blockIdx.y * 8 + ty;
    float4 v = g_states[k * BB + col];
    float y1 = v.x, y2 = v.y, y3 = v.z, y4 = v.w;
    int n0 = 5 + LBLK * k;
    int nsteps = min(LBLK, TT - n0);   // 256, last block 251
    const float* sp = g_s + col;
    float*       op = out + col;
    #pragma unroll 4
    for (int i = 0; i < nsteps; i++) {
        int n = n0 + i;
        float sv = sp[(size_t)n * BB];
        float t = fmaf(na4, y4, sv);   // old values first: keeps critical path = 1 FMA on y1
        t = fmaf(na3, y3, t);
        t = fmaf(na2, y2, t);
        float y = fmaf(na1, y1, t);
        op[(size_t)n * BB] = y;
        y4 = y3; y3 = y2; y2 = y1; y1 = y;
    }
}

// ---------------- host: Butterworth design (exact replica of reference algorithm, f64) ----------------
static void compute_butter(double* bc, double* ac) {
    const double PI = 3.14159265358979323846264338327950288;
    const int order = 4;
    const double wn = 25e9 / (0.5 / 1e-12);   // 0.05
    double warped = 4.0 * tan(PI * wn / 2.0);
    std::complex<double> p[4];
    for (int k = 1; k <= order; k++) {
        double ang = PI * (2.0 * k + order - 1.0) / (2.0 * order);
        p[k - 1] = warped * std::complex<double>(cos(ang), sin(ang));
    }
    double gain = warped * warped * warped * warped;
    std::complex<double> fs2(4.0, 0.0);
    std::complex<double> pz[4], prod(1.0, 0.0);
    for (int i = 0; i < 4; i++) { pz[i] = (fs2 + p[i]) / (fs2 - p[i]); prod *= (fs2 - p[i]); }
    double gz = gain * std::real(std::complex<double>(1.0, 0.0) / prod);
    const double binom[5] = {1, 4, 6, 4, 1};
    for (int i = 0; i < 5; i++) bc[i] = gz * binom[i];
    std::complex<double> c[5] = {{1,0},{0,0},{0,0},{0,0},{0,0}};
    for (int i = 0; i < 4; i++)
        for (int j = i + 1; j >= 1; j--)
            c[j] -= pz[i] * c[j - 1];
    for (int i = 0; i < 5; i++) ac[i] = std::real(c[i]);
}

extern "C" void kernel_launch(void* const* d_in, const int* in_sizes, int n_in,
                              void* d_out, int out_size) {
    const float* sig   = (const float*)d_in[0];   // (16384, 512) f32
    const float* noise = (const float*)d_in[1];   // (512, 1, 16388) f32
    float* out = (float*)d_out;                   // (16384, 512) f32

    // Filter design + block-parallel IIR tables (host f64, runs only at capture; deterministic).
    double bc[5], ac[5];
    compute_butter(bc, ac);

    double gd[LBLK];
    gd[0] = 1.0;
    for (int j = 1; j < LBLK; j++) {
        double v = -ac[1] * gd[j - 1];
        if (j >= 2) v -= ac[2] * gd[j - 2];
        if (j >= 3) v -= ac[3] * gd[j - 3];
        if (j >= 4) v -= ac[4] * gd[j - 4];
        gd[j] = v;
    }
    GP gp;
    for (int j = 0; j < LBLK; j++) gp.g[j] = (float)gd[j];

    ALP alp;
    for (int cidx = 0; cidx < 4; cidx++) {   // column cidx of A^LBLK via state simulation
        double v0 = (cidx == 0), v1 = (cidx == 1), v2 = (cidx == 2), v3 = (cidx == 3);
        for (int it = 0; it < LBLK; it++) {
            double nv = -(ac[1] * v0 + ac[2] * v1 + ac[3] * v2 + ac[4] * v3);
            v3 = v2; v2 = v1; v1 = v0; v0 = nv;
        }
        alp.al[0 * 4 + cidx] = (float)v0;
        alp.al[1 * 4 + cidx] = (float)v1;
        alp.al[2 * 4 + cidx] = (float)v2;
        alp.al[3 * 4 + cidx] = (float)v3;
    }

    const double Qc = 1.602176563e-19, KBc = 1.3806488e-23, Tk = 300.0;
    const double BR = 5e10, DARK = 1e-10, RL = 1e6;
    double C1  = 2.0 * Qc * BR;
    double ADD = C1 * DARK + 4.0 * KBc * Tk * BR / RL;

    k_sd   <<<TPAD, 128>>>(sig, (float)C1, (float)ADD);
    k_fir  <<<dim3(16, 256), dim3(32, 8)>>>(sig, noise, out,
              (float)bc[0], (float)bc[1], (float)bc[2], (float)bc[3], (float)bc[4]);
    k_ua   <<<dim3(16, 16), dim3(32, 4)>>>(gp);
    k_chain<<<4, 128>>>(alp);
    k_iir  <<<dim3(16, 8), dim3(32, 8)>>>(out,
              (float)(-ac[1]), (float)(-ac[2]), (float)(-ac[3]), (float)(-ac[4]));
}

// round 5
// speedup vs baseline: 1.1715x; 1.1715x over previous
#include <cuda_runtime.h>
#include <math.h>
#include <complex>

// ---------------- problem constants ----------------
#define TT    16384          // time steps (output rows)
#define BB    512            // batch columns
#define TPAD  16388          // TT + K - 1 (K = 5)
#define LBLK  256            // IIR parallel block length
#define NBLK  64             // number of IIR blocks
#define NU    63             // number of block-transition vectors u_0..u_62

// ---------------- device scratch (static, allocation-free) ----------------
__device__ float  g_sd[TPAD];          // noise std-dev per padded time step
__device__ float  g_s[TT * BB];        // FIR output s[t][b]
__device__ float  g_u[4 * NU * BB];    // block-transition input vectors

struct GP  { float g[LBLK]; };   // impulse response of 1/A (truncated)
struct ALP { float al[16]; };    // M = A^LBLK  (row-major 4x4), ||M|| ~ 1e-5

// ---------------- kernel 1: noise std-dev per time step ----------------
// sd[t] = sqrt(C1*(mean_b xp[b,t]) + ADD), xp row t maps to signal row t-4 (zero for t<4)
__global__ __launch_bounds__(128) void k_sd(const float* __restrict__ sig,
                                            float c1, float addc) {
    int t = blockIdx.x;
    float sum = 0.f;
    if (t >= 4) {
        const float4* row = (const float4*)(sig + (size_t)(t - 4) * BB);
        float4 v = row[threadIdx.x];
        sum = (v.x + v.y) + (v.z + v.w);
    }
    #pragma unroll
    for (int o = 16; o; o >>= 1) sum += __shfl_down_sync(0xffffffffu, sum, o);
    __shared__ float red[4];
    if ((threadIdx.x & 31) == 0) red[threadIdx.x >> 5] = sum;
    __syncthreads();
    if (threadIdx.x == 0) {
        float tot = (red[0] + red[1]) + (red[2] + red[3]);
        g_sd[t] = sqrtf(fmaf(c1, tot * (1.f / 512.f), addc));
    }
}

// ---------------- kernel 2: xn + 5-tap FIR -> s[t][b]  (also out rows 0..4) ----------------
// s[t,b] = sum_k bk * ( sd[t+k]*noise[b][t+k] + signal[t+k-4][b] )
__global__ __launch_bounds__(256) void k_fir(const float* __restrict__ sig,
                                             const float* __restrict__ noise,
                                             float* __restrict__ out,
                                             float b0, float b1, float b2, float b3, float b4) {
    __shared__ float nz[32][69];   // [col][j], stride 69 -> conflict-free transpose reads
    __shared__ float sg[68][33];   // [j][col]
    __shared__ float sds[68];
    int tx = threadIdx.x, ty = threadIdx.y;
    int col0 = blockIdx.x * 32;
    int t0   = blockIdx.y * 64;

    // noise tile: rows = columns of the problem, coalesced along t
    #pragma unroll
    for (int i = 0; i < 4; i++) {
        int c = ty * 4 + i;
        const float* nrow = noise + (size_t)(col0 + c) * TPAD + t0;
        for (int j = tx; j < 68; j += 32) nz[c][j] = nrow[j];
    }
    // signal tile: coalesced along b
    for (int r = ty; r < 68; r += 8) {
        int trow = t0 - 4 + r;
        sg[r][tx] = (trow >= 0) ? sig[(size_t)trow * BB + col0 + tx] : 0.f;
    }
    int tid = ty * 32 + tx;
    if (tid < 68) sds[tid] = g_sd[t0 + tid];
    __syncthreads();

    #pragma unroll
    for (int i = 0; i < 8; i++) {
        int tt = ty + 8 * i;                       // local t 0..63
        float x0 = fmaf(sds[tt + 0], nz[tx][tt + 0], sg[tt + 0][tx]);
        float x1 = fmaf(sds[tt + 1], nz[tx][tt + 1], sg[tt + 1][tx]);
        float x2 = fmaf(sds[tt + 2], nz[tx][tt + 2], sg[tt + 2][tx]);
        float x3 = fmaf(sds[tt + 3], nz[tx][tt + 3], sg[tt + 3][tx]);
        float x4 = fmaf(sds[tt + 4], nz[tx][tt + 4], sg[tt + 4][tx]);
        float acc = b0 * x0;
        acc = fmaf(b1, x1, acc);
        acc = fmaf(b2, x2, acc);
        acc = fmaf(b3, x3, acc);
        acc = fmaf(b4, x4, acc);
        int t = t0 + tt;
        g_s[(size_t)t * BB + col0 + tx] = acc;
        if (t < 5) out[(size_t)t * BB + col0 + tx] = acc;   // out rows 0..4 = s rows 0..4
    }
}

// ---------------- pass A: per-(col, block) FIRs with g (block input vectors u_k) ----------------
// u_k[c] = sum_{i=0}^{LBLK-1-c} g_i * s[e - c - i],  e = 4 + LBLK*(k+1)
__global__ __launch_bounds__(128) void k_ua(GP P) {
    __shared__ float gs[LBLK];
    int tx = threadIdx.x, ty = threadIdx.y;
    int tid = ty * 32 + tx;
    for (int i = tid; i < LBLK; i += 128) gs[i] = P.g[i];
    __syncthreads();

    int k = blockIdx.y * 4 + ty;
    if (k >= NU) return;
    int col = blockIdx.x * 32 + tx;
    const float* sp = g_s + col;
    int e = 4 + LBLK * (k + 1);

    float u0, u1, u2, u3 = 0.f;
    float sv;
    sv = sp[(size_t)e * BB];
    u0 = gs[0] * sv;
    sv = sp[(size_t)(e - 1) * BB];
    u0 = fmaf(gs[1], sv, u0); u1 = gs[0] * sv;
    sv = sp[(size_t)(e - 2) * BB];
    u0 = fmaf(gs[2], sv, u0); u1 = fmaf(gs[1], sv, u1); u2 = gs[0] * sv;
    #pragma unroll 4
    for (int j = 3; j < LBLK; j++) {
        float s2 = sp[(size_t)(e - j) * BB];
        u0 = fmaf(gs[j],     s2, u0);
        u1 = fmaf(gs[j - 1], s2, u1);
        u2 = fmaf(gs[j - 2], s2, u2);
        u3 = fmaf(gs[j - 3], s2, u3);
    }
    g_u[0 * (NU * BB) + k * BB + col] = u0;
    g_u[1 * (NU * BB) + k * BB + col] = u1;
    g_u[2 * (NU * BB) + k * BB + col] = u2;
    g_u[3 * (NU * BB) + k * BB + col] = u3;
}

// ---------------- pass C: within-block IIR, states computed inline ----------------
// Exact: v_{k} = M v_{k-1} + u_{k-1}, M = A^256 with ||M|| ~ 1e-5.
// Truncation: v_k = u_{k-1} + M u_{k-2}  (k>=2), error O(||M||^2) ~ 1e-10.
// k=1 exact: v_1 = u_0 + M v_0.  k=0: v_0 from s rows 1..4.
__global__ __launch_bounds__(256) void k_iir(float* __restrict__ out, ALP P,
                                             float na1, float na2, float na3, float na4) {
    int tx = threadIdx.x, ty = threadIdx.y;
    int col = blockIdx.x * 32 + tx;
    int k   = blockIdx.y * 8 + ty;

    float y1, y2, y3, y4;
    if (k == 0) {
        y1 = g_s[4 * BB + col];
        y2 = g_s[3 * BB + col];
        y3 = g_s[2 * BB + col];
        y4 = g_s[1 * BB + col];
    } else {
        // previous-state proxy p (v_0 for k==1, u_{k-2} for k>=2)
        float p0, p1, p2, p3;
        if (k == 1) {
            p0 = g_s[4 * BB + col];
            p1 = g_s[3 * BB + col];
            p2 = g_s[2 * BB + col];
            p3 = g_s[1 * BB + col];
        } else {
            int km2 = k - 2;
            p0 = g_u[0 * (NU * BB) + km2 * BB + col];
            p1 = g_u[1 * (NU * BB) + km2 * BB + col];
            p2 = g_u[2 * (NU * BB) + km2 * BB + col];
            p3 = g_u[3 * (NU * BB) + km2 * BB + col];
        }
        int km1 = k - 1;
        const float* al = P.al;
        float w;
        w = g_u[0 * (NU * BB) + km1 * BB + col];
        w = fmaf(al[0],  p0, w); w = fmaf(al[1],  p1, w);
        w = fmaf(al[2],  p2, w); y1 = fmaf(al[3],  p3, w);
        w = g_u[1 * (NU * BB) + km1 * BB + col];
        w = fmaf(al[4],  p0, w); w = fmaf(al[5],  p1, w);
        w = fmaf(al[6],  p2, w); y2 = fmaf(al[7],  p3, w);
        w = g_u[2 * (NU * BB) + km1 * BB + col];
        w = fmaf(al[8],  p0, w); w = fmaf(al[9],  p1, w);
        w = fmaf(al[10], p2, w); y3 = fmaf(al[11], p3, w);
        w = g_u[3 * (NU * BB) + km1 * BB + col];
        w = fmaf(al[12], p0, w); w = fmaf(al[13], p1, w);
        w = fmaf(al[14], p2, w); y4 = fmaf(al[15], p3, w);
    }

    int n0 = 5 + LBLK * k;
    int nsteps = min(LBLK, TT - n0);   // 256, last block 251
    const float* sp = g_s + col;
    float*       op = out + col;
    #pragma unroll 4
    for (int i = 0; i < nsteps; i++) {
        int n = n0 + i;
        float sv = sp[(size_t)n * BB];
        float t = fmaf(na4, y4, sv);   // old values first: critical path = 1 FMA on y1
        t = fmaf(na3, y3, t);
        t = fmaf(na2, y2, t);
        float y = fmaf(na1, y1, t);
        op[(size_t)n * BB] = y;
        y4 = y3; y3 = y2; y2 = y1; y1 = y;
    }
}

// ---------------- host: Butterworth design (exact replica of reference algorithm, f64) ----------------
static void compute_butter(double* bc, double* ac) {
    const double PI = 3.14159265358979323846264338327950288;
    const int order = 4;
    const double wn = 25e9 / (0.5 / 1e-12);   // 0.05
    double warped = 4.0 * tan(PI * wn / 2.0);
    std::complex<double> p[4];
    for (int k = 1; k <= order; k++) {
        double ang = PI * (2.0 * k + order - 1.0) / (2.0 * order);
        p[k - 1] = warped * std::complex<double>(cos(ang), sin(ang));
    }
    double gain = warped * warped * warped * warped;
    std::complex<double> fs2(4.0, 0.0);
    std::complex<double> pz[4], prod(1.0, 0.0);
    for (int i = 0; i < 4; i++) { pz[i] = (fs2 + p[i]) / (fs2 - p[i]); prod *= (fs2 - p[i]); }
    double gz = gain * std::real(std::complex<double>(1.0, 0.0) / prod);
    const double binom[5] = {1, 4, 6, 4, 1};
    for (int i = 0; i < 5; i++) bc[i] = gz * binom[i];
    std::complex<double> c[5] = {{1,0},{0,0},{0,0},{0,0},{0,0}};
    for (int i = 0; i < 4; i++)
        for (int j = i + 1; j >= 1; j--)
            c[j] -= pz[i] * c[j - 1];
    for (int i = 0; i < 5; i++) ac[i] = std::real(c[i]);
}

extern "C" void kernel_launch(void* const* d_in, const int* in_sizes, int n_in,
                              void* d_out, int out_size) {
    const float* sig   = (const float*)d_in[0];   // (16384, 512) f32
    const float* noise = (const float*)d_in[1];   // (512, 1, 16388) f32
    float* out = (float*)d_out;                   // (16384, 512) f32

    // Filter design + block-parallel IIR tables (host f64, runs only at capture; deterministic).
    double bc[5], ac[5];
    compute_butter(bc, ac);

    double gd[LBLK];
    gd[0] = 1.0;
    for (int j = 1; j < LBLK; j++) {
        double v = -ac[1] * gd[j - 1];
        if (j >= 2) v -= ac[2] * gd[j - 2];
        if (j >= 3) v -= ac[3] * gd[j - 3];
        if (j >= 4) v -= ac[4] * gd[j - 4];
        gd[j] = v;
    }
    GP gp;
    for (int j = 0; j < LBLK; j++) gp.g[j] = (float)gd[j];

    ALP alp;
    for (int cidx = 0; cidx < 4; cidx++) {   // column cidx of M = A^LBLK via state simulation
        double v0 = (cidx == 0), v1 = (cidx == 1), v2 = (cidx == 2), v3 = (cidx == 3);
        for (int it = 0; it < LBLK; it++) {
            double nv = -(ac[1] * v0 + ac[2] * v1 + ac[3] * v2 + ac[4] * v3);
            v3 = v2; v2 = v1; v1 = v0; v0 = nv;
        }
        alp.al[0 * 4 + cidx] = (float)v0;
        alp.al[1 * 4 + cidx] = (float)v1;
        alp.al[2 * 4 + cidx] = (float)v2;
        alp.al[3 * 4 + cidx] = (float)v3;
    }

    const double Qc = 1.602176563e-19, KBc = 1.3806488e-23, Tk = 300.0;
    const double BR = 5e10, DARK = 1e-10, RL = 1e6;
    double C1  = 2.0 * Qc * BR;
    double ADD = C1 * DARK + 4.0 * KBc * Tk * BR / RL;

    k_sd <<<TPAD, 128>>>(sig, (float)C1, (float)ADD);
    k_fir<<<dim3(16, 256), dim3(32, 8)>>>(sig, noise, out,
            (float)bc[0], (float)bc[1], (float)bc[2], (float)bc[3], (float)bc[4]);
    k_ua <<<dim3(16, 16), dim3(32, 4)>>>(gp);
    k_iir<<<dim3(16, 8), dim3(32, 8)>>>(out, alp,
            (float)(-ac[1]), (float)(-ac[2]), (float)(-ac[3]), (float)(-ac[4]));
}